// round 1
// baseline (speedup 1.0000x reference)
#include <cuda_runtime.h>
#include <cstdint>
#include <cstddef>

// Problem constants
#define BATCH 8
#define SEQ   2048
#define DIM   1024
#define MTOT  (BATCH*SEQ)   // 16384

// GEMM tiling
#define BM 128
#define BN 128
#define BK 32
#define STRIDE 36  // BK + 4 pad (conflict-free fragment loads)

// Scratch (device globals: allocation-free scratch per harness rules)
__device__ float g_Q[(size_t)MTOT*DIM];
__device__ float g_K[(size_t)MTOT*DIM];
__device__ float g_V[(size_t)MTOT*DIM];
__device__ float g_S[(size_t)BATCH*SEQ*SEQ];
__device__ float g_Wt[(size_t)MTOT*DIM];

__device__ __forceinline__ float to_tf32(float x) {
    uint32_t u;
    asm("cvt.rna.tf32.f32 %0, %1;" : "=r"(u) : "f"(x));
    return __uint_as_float(u);
}

__device__ __forceinline__ void mma_tf32(float c[4], const uint32_t a[4], const uint32_t b[2]) {
    asm("mma.sync.aligned.m16n8k8.row.col.f32.tf32.tf32.f32 "
        "{%0,%1,%2,%3},{%4,%5,%6,%7},{%8,%9},{%0,%1,%2,%3};"
        : "+f"(c[0]), "+f"(c[1]), "+f"(c[2]), "+f"(c[3])
        : "r"(a[0]), "r"(a[1]), "r"(a[2]), "r"(a[3]), "r"(b[0]), "r"(b[1]));
}

// C = A * op(B) * scale (+ bias[col]) (+ resid), fp32 in, tf32 mma, fp32 out.
// TRANSB=true : B is [N,K] row-major (C = A B^T)   — "NT"
// TRANSB=false: B is [K,N] row-major (C = A B)     — "NN"
// M,N multiples of 128; K multiple of 32 (no bounds checks — all shapes comply).
template <bool TRANSB>
__global__ __launch_bounds__(256) void gemm_k(
    const float* __restrict__ A, const float* __restrict__ Bm,
    const float* __restrict__ bias, const float* __restrict__ resid,
    float* __restrict__ C,
    int lda, int ldb, int ldc, int K, float scale,
    long sA, long sB, long sC)
{
    __shared__ float As[BM * STRIDE];
    __shared__ float Bs[BN * STRIDE];

    const int bz = blockIdx.z;
    A  += (long)bz * sA;
    Bm += (long)bz * sB;
    C  += (long)bz * sC;

    const int m0 = blockIdx.y * BM;
    const int n0 = blockIdx.x * BN;
    const int tid  = threadIdx.x;
    const int wid  = tid >> 5;
    const int lane = tid & 31;
    const int wm = (wid >> 2) * 64;   // warp m offset (2 warps in m)
    const int wn = (wid & 3) * 32;    // warp n offset (4 warps in n)
    const int lg = lane >> 2;         // 0..7
    const int lq = lane & 3;          // 0..3

    float acc[4][4][4];
#pragma unroll
    for (int i = 0; i < 4; i++)
#pragma unroll
        for (int j = 0; j < 4; j++)
#pragma unroll
            for (int r = 0; r < 4; r++) acc[i][j][r] = 0.f;

    const int ar = tid >> 3;        // 0..31 (row within 32-row group)
    const int ac = (tid & 7) * 4;   // 0..28 (k, float4)
    const int bnIdx = tid & 127;    // NN: n index
    const int bkBase = (tid >> 7) * 16;  // NN: k group base

    for (int k0 = 0; k0 < K; k0 += BK) {
        // --- A tile: As[m][k], float4 global loads along k ---
#pragma unroll
        for (int j = 0; j < 4; j++) {
            int r = ar + j * 32;
            float4 v = *reinterpret_cast<const float4*>(A + (long)(m0 + r) * lda + k0 + ac);
            v.x = to_tf32(v.x); v.y = to_tf32(v.y); v.z = to_tf32(v.z); v.w = to_tf32(v.w);
            *reinterpret_cast<float4*>(&As[r * STRIDE + ac]) = v;
        }
        // --- B tile: Bs[n][k] ---
        if (TRANSB) {
#pragma unroll
            for (int j = 0; j < 4; j++) {
                int r = ar + j * 32;
                float4 v = *reinterpret_cast<const float4*>(Bm + (long)(n0 + r) * ldb + k0 + ac);
                v.x = to_tf32(v.x); v.y = to_tf32(v.y); v.z = to_tf32(v.z); v.w = to_tf32(v.w);
                *reinterpret_cast<float4*>(&Bs[r * STRIDE + ac]) = v;
            }
        } else {
#pragma unroll
            for (int j = 0; j < 4; j++) {
                int kk = bkBase + j * 4;
                float4 v;
                v.x = Bm[(long)(k0 + kk + 0) * ldb + n0 + bnIdx];
                v.y = Bm[(long)(k0 + kk + 1) * ldb + n0 + bnIdx];
                v.z = Bm[(long)(k0 + kk + 2) * ldb + n0 + bnIdx];
                v.w = Bm[(long)(k0 + kk + 3) * ldb + n0 + bnIdx];
                v.x = to_tf32(v.x); v.y = to_tf32(v.y); v.z = to_tf32(v.z); v.w = to_tf32(v.w);
                *reinterpret_cast<float4*>(&Bs[bnIdx * STRIDE + kk]) = v;
            }
        }
        __syncthreads();

#pragma unroll
        for (int s = 0; s < 4; s++) {
            uint32_t af[4][4];
            uint32_t bf[4][2];
            const int kk = s * 8 + lq;
#pragma unroll
            for (int i = 0; i < 4; i++) {
                int row = wm + i * 16 + lg;
                af[i][0] = __float_as_uint(As[row * STRIDE + kk]);
                af[i][1] = __float_as_uint(As[(row + 8) * STRIDE + kk]);
                af[i][2] = __float_as_uint(As[row * STRIDE + kk + 4]);
                af[i][3] = __float_as_uint(As[(row + 8) * STRIDE + kk + 4]);
            }
#pragma unroll
            for (int j = 0; j < 4; j++) {
                int nn = wn + j * 8 + lg;
                bf[j][0] = __float_as_uint(Bs[nn * STRIDE + kk]);
                bf[j][1] = __float_as_uint(Bs[nn * STRIDE + kk + 4]);
            }
#pragma unroll
            for (int i = 0; i < 4; i++)
#pragma unroll
                for (int j = 0; j < 4; j++)
                    mma_tf32(acc[i][j], af[i], bf[j]);
        }
        __syncthreads();
    }

    // --- epilogue ---
#pragma unroll
    for (int i = 0; i < 4; i++) {
        int r = m0 + wm + i * 16 + lg;
#pragma unroll
        for (int j = 0; j < 4; j++) {
            int c = n0 + wn + j * 8 + lq * 2;
            float v0 = acc[i][j][0] * scale;
            float v1 = acc[i][j][1] * scale;
            float v2 = acc[i][j][2] * scale;
            float v3 = acc[i][j][3] * scale;
            if (bias) {
                float b0 = bias[c], b1 = bias[c + 1];
                v0 += b0; v1 += b1; v2 += b0; v3 += b1;
            }
            if (resid) {
                v0 += resid[(long)r * ldc + c];
                v1 += resid[(long)r * ldc + c + 1];
                v2 += resid[(long)(r + 8) * ldc + c];
                v3 += resid[(long)(r + 8) * ldc + c + 1];
            }
            C[(long)r * ldc + c]           = v0;
            C[(long)r * ldc + c + 1]       = v1;
            C[(long)(r + 8) * ldc + c]     = v2;
            C[(long)(r + 8) * ldc + c + 1] = v3;
        }
    }
}

// Row softmax over rows of length 2048 (one block per row, 256 threads x 8 elems)
__global__ __launch_bounds__(256) void softmax_k(float* __restrict__ S)
{
    float* p = S + (long)blockIdx.x * SEQ;
    const int tid = threadIdx.x;
    float vals[8];
    float mx = -1e30f;
#pragma unroll
    for (int i = 0; i < 8; i++) {
        vals[i] = p[tid + i * 256];
        mx = fmaxf(mx, vals[i]);
    }
#pragma unroll
    for (int o = 16; o; o >>= 1) mx = fmaxf(mx, __shfl_xor_sync(0xFFFFFFFFu, mx, o));
    __shared__ float redm[8];
    if ((tid & 31) == 0) redm[tid >> 5] = mx;
    __syncthreads();
    mx = redm[0];
#pragma unroll
    for (int i = 1; i < 8; i++) mx = fmaxf(mx, redm[i]);

    float sum = 0.f;
#pragma unroll
    for (int i = 0; i < 8; i++) {
        vals[i] = expf(vals[i] - mx);
        sum += vals[i];
    }
#pragma unroll
    for (int o = 16; o; o >>= 1) sum += __shfl_xor_sync(0xFFFFFFFFu, sum, o);
    __shared__ float reds[8];
    if ((tid & 31) == 0) reds[tid >> 5] = sum;
    __syncthreads();
    sum = 0.f;
#pragma unroll
    for (int i = 0; i < 8; i++) sum += reds[i];
    const float inv = 1.f / sum;
#pragma unroll
    for (int i = 0; i < 8; i++) p[tid + i * 256] = vals[i] * inv;
}

// In-place LayerNorm over rows of length 1024 (one block/row, 256 threads x float4)
__global__ __launch_bounds__(256) void ln_k(float* __restrict__ y,
                                            const float* __restrict__ gamma,
                                            const float* __restrict__ beta)
{
    float* p = y + (long)blockIdx.x * DIM;
    const int tid = threadIdx.x;
    float4 v = reinterpret_cast<float4*>(p)[tid];
    float s  = v.x + v.y + v.z + v.w;
    float sq = v.x * v.x + v.y * v.y + v.z * v.z + v.w * v.w;
#pragma unroll
    for (int o = 16; o; o >>= 1) {
        s  += __shfl_xor_sync(0xFFFFFFFFu, s, o);
        sq += __shfl_xor_sync(0xFFFFFFFFu, sq, o);
    }
    __shared__ float rs_[8], rq_[8];
    if ((tid & 31) == 0) { rs_[tid >> 5] = s; rq_[tid >> 5] = sq; }
    __syncthreads();
    s = 0.f; sq = 0.f;
#pragma unroll
    for (int i = 0; i < 8; i++) { s += rs_[i]; sq += rq_[i]; }
    const float mean = s * (1.f / DIM);
    const float var  = sq * (1.f / DIM) - mean * mean;
    const float inv  = rsqrtf(var + 1e-5f);
    const float4 g = reinterpret_cast<const float4*>(gamma)[tid];
    const float4 b = reinterpret_cast<const float4*>(beta)[tid];
    v.x = (v.x - mean) * inv * g.x + b.x;
    v.y = (v.y - mean) * inv * g.y + b.y;
    v.z = (v.z - mean) * inv * g.z + b.z;
    v.w = (v.w - mean) * inv * g.w + b.w;
    reinterpret_cast<float4*>(p)[tid] = v;
}

extern "C" void kernel_launch(void* const* d_in, const int* in_sizes, int n_in,
                              void* d_out, int out_size)
{
    const float* x     = (const float*)d_in[0];
    const float* Wq    = (const float*)d_in[1];
    const float* bq    = (const float*)d_in[2];
    const float* Wk    = (const float*)d_in[3];
    const float* bk    = (const float*)d_in[4];
    const float* Wv    = (const float*)d_in[5];
    const float* bv    = (const float*)d_in[6];
    const float* Wo    = (const float*)d_in[7];
    const float* bo    = (const float*)d_in[8];
    const float* gamma = (const float*)d_in[9];
    const float* beta  = (const float*)d_in[10];
    float* out = (float*)d_out;

    void *pQ, *pK, *pV, *pS, *pW;
    cudaGetSymbolAddress(&pQ, g_Q);
    cudaGetSymbolAddress(&pK, g_K);
    cudaGetSymbolAddress(&pV, g_V);
    cudaGetSymbolAddress(&pS, g_S);
    cudaGetSymbolAddress(&pW, g_Wt);
    float* Q  = (float*)pQ;
    float* Kb = (float*)pK;
    float* V  = (float*)pV;
    float* Sc = (float*)pS;
    float* Wt = (float*)pW;

    dim3 blk(256);

    // 1) QKV projections: [16384,1024] = x[16384,1024] @ W^T + b
    dim3 gP(DIM / BN, MTOT / BM, 1);
    gemm_k<true><<<gP, blk>>>(x, Wq, bq, nullptr, Q,  DIM, DIM, DIM, DIM, 1.f, 0, 0, 0);
    gemm_k<true><<<gP, blk>>>(x, Wk, bk, nullptr, Kb, DIM, DIM, DIM, DIM, 1.f, 0, 0, 0);
    gemm_k<true><<<gP, blk>>>(x, Wv, bv, nullptr, V,  DIM, DIM, DIM, DIM, 1.f, 0, 0, 0);

    // 2) scores = Q K^T * (1/sqrt(D)), batched over 8
    dim3 gS_(SEQ / BN, SEQ / BM, BATCH);
    gemm_k<true><<<gS_, blk>>>(Q, Kb, nullptr, nullptr, Sc,
                               DIM, DIM, SEQ, DIM, 0.03125f,
                               (long)SEQ * DIM, (long)SEQ * DIM, (long)SEQ * SEQ);

    // 3) softmax rows
    softmax_k<<<BATCH * SEQ, blk>>>(Sc);

    // 4) weighted = P V (NN), batched
    dim3 gW_(DIM / BN, SEQ / BM, BATCH);
    gemm_k<false><<<gW_, blk>>>(Sc, V, nullptr, nullptr, Wt,
                                SEQ, DIM, DIM, SEQ, 1.f,
                                (long)SEQ * SEQ, (long)SEQ * DIM, (long)SEQ * DIM);

    // 5) out = weighted Wo^T + bo + x  (residual fused)
    gemm_k<true><<<gP, blk>>>(Wt, Wo, bo, x, out, DIM, DIM, DIM, DIM, 1.f, 0, 0, 0);

    // 6) LayerNorm in place
    ln_k<<<MTOT, blk>>>(out, gamma, beta);
}

// round 2
// speedup vs baseline: 1.8763x; 1.8763x over previous
#include <cuda_runtime.h>
#include <cuda_bf16.h>
#include <cstdint>
#include <cstddef>

#define BATCH 8
#define SEQ   2048
#define DIM   1024
#define MTOT  (BATCH*SEQ)   // 16384

#define BM 128
#define BN 128
#define BK 32
#define KSTRIDE 40                  // halves per smem row (32 + 8 pad, keeps 16B align)
#define STAGE_ELE (BM*KSTRIDE)      // 5120 halves per tile stage

// ---- scratch (device globals; allocation-free per harness rules) ----
__device__ __nv_bfloat16 g_xb[(size_t)MTOT*DIM];
__device__ __nv_bfloat16 g_Wqb[DIM*DIM], g_Wkb[DIM*DIM], g_Wvb[DIM*DIM], g_Wob[DIM*DIM];
__device__ __nv_bfloat16 g_Qb[(size_t)MTOT*DIM];
__device__ __nv_bfloat16 g_Kb[(size_t)MTOT*DIM];
__device__ __nv_bfloat16 g_Vb[(size_t)MTOT*DIM];
__device__ __nv_bfloat16 g_Vt[(size_t)MTOT*DIM];
__device__ float         g_S [(size_t)BATCH*SEQ*SEQ];
__device__ __nv_bfloat16 g_P [(size_t)BATCH*SEQ*SEQ];
__device__ __nv_bfloat16 g_Wt[(size_t)MTOT*DIM];

// ---- helpers ----
__device__ __forceinline__ void cp16(void* smem, const void* gmem) {
    uint32_t s = (uint32_t)__cvta_generic_to_shared(smem);
    asm volatile("cp.async.cg.shared.global [%0], [%1], 16;\n" :: "r"(s), "l"(gmem));
}
__device__ __forceinline__ void cp_commit() { asm volatile("cp.async.commit_group;\n"); }
template<int N> __device__ __forceinline__ void cp_wait() {
    asm volatile("cp.async.wait_group %0;\n" :: "n"(N));
}

__device__ __forceinline__ void mma_bf16(float c[4], const uint32_t a[4], const uint32_t b[2]) {
    asm("mma.sync.aligned.m16n8k16.row.col.f32.bf16.bf16.f32 "
        "{%0,%1,%2,%3},{%4,%5,%6,%7},{%8,%9},{%0,%1,%2,%3};"
        : "+f"(c[0]), "+f"(c[1]), "+f"(c[2]), "+f"(c[3])
        : "r"(a[0]), "r"(a[1]), "r"(a[2]), "r"(a[3]), "r"(b[0]), "r"(b[1]));
}

// ---- NT bf16 GEMM: C = A[M,K] * B[N,K]^T * scale (+bias) (+resid) ----
// M,N multiples of 128; K multiple of 32. 2-stage cp.async pipeline.
template<typename OutT, bool HAS_BIAS, bool HAS_RESID>
__global__ __launch_bounds__(256, 2) void gemm_bf(
    const __nv_bfloat16* __restrict__ A, const __nv_bfloat16* __restrict__ B,
    const float* __restrict__ bias, const float* __restrict__ resid,
    OutT* __restrict__ C,
    int lda, int ldb, int ldc, int K, float scale,
    long sA, long sB, long sC)
{
    __shared__ __nv_bfloat16 As[2 * STAGE_ELE];
    __shared__ __nv_bfloat16 Bs[2 * STAGE_ELE];

    const int bz = blockIdx.z;
    A += (long)bz * sA;
    B += (long)bz * sB;
    C += (long)bz * sC;

    const int m0 = blockIdx.y * BM;
    const int n0 = blockIdx.x * BN;
    const int tid  = threadIdx.x;
    const int wid  = tid >> 5;
    const int lane = tid & 31;
    const int wm = (wid >> 2) * 64;
    const int wn = (wid & 3) * 32;
    const int lg = lane >> 2;
    const int lq = lane & 3;

    // loader mapping: 64 rows/pass, 4x 16B chunks per row
    const int lr = tid >> 2;        // 0..63
    const int lc = (tid & 3) * 8;   // half offset: 0,8,16,24

    float acc[4][4][4];
#pragma unroll
    for (int i = 0; i < 4; i++)
#pragma unroll
        for (int j = 0; j < 4; j++)
#pragma unroll
            for (int r = 0; r < 4; r++) acc[i][j][r] = 0.f;

    const int KT = K / BK;

    // stage loader
    auto load_stage = [&](int buf, int kt) {
        const int k0 = kt * BK;
        __nv_bfloat16* as = As + buf * STAGE_ELE;
        __nv_bfloat16* bs = Bs + buf * STAGE_ELE;
#pragma unroll
        for (int p = 0; p < 2; p++) {
            int row = lr + p * 64;
            cp16(&as[row * KSTRIDE + lc], A + (long)(m0 + row) * lda + k0 + lc);
            cp16(&bs[row * KSTRIDE + lc], B + (long)(n0 + row) * ldb + k0 + lc);
        }
    };

    load_stage(0, 0);
    cp_commit();

    for (int kt = 0; kt < KT; kt++) {
        if (kt + 1 < KT) {
            load_stage((kt + 1) & 1, kt + 1);
            cp_commit();
            cp_wait<1>();
        } else {
            cp_wait<0>();
        }
        __syncthreads();

        const __nv_bfloat16* as = As + (kt & 1) * STAGE_ELE;
        const __nv_bfloat16* bs = Bs + (kt & 1) * STAGE_ELE;
#pragma unroll
        for (int s = 0; s < 2; s++) {
            const int kk = s * 16 + lq * 2;
            uint32_t af[4][4];
            uint32_t bfr[4][2];
#pragma unroll
            for (int i = 0; i < 4; i++) {
                int row = wm + i * 16 + lg;
                af[i][0] = *reinterpret_cast<const uint32_t*>(&as[row * KSTRIDE + kk]);
                af[i][1] = *reinterpret_cast<const uint32_t*>(&as[(row + 8) * KSTRIDE + kk]);
                af[i][2] = *reinterpret_cast<const uint32_t*>(&as[row * KSTRIDE + kk + 8]);
                af[i][3] = *reinterpret_cast<const uint32_t*>(&as[(row + 8) * KSTRIDE + kk + 8]);
            }
#pragma unroll
            for (int j = 0; j < 4; j++) {
                int nn = wn + j * 8 + lg;
                bfr[j][0] = *reinterpret_cast<const uint32_t*>(&bs[nn * KSTRIDE + kk]);
                bfr[j][1] = *reinterpret_cast<const uint32_t*>(&bs[nn * KSTRIDE + kk + 8]);
            }
#pragma unroll
            for (int i = 0; i < 4; i++)
#pragma unroll
                for (int j = 0; j < 4; j++)
                    mma_bf16(acc[i][j], af[i], bfr[j]);
        }
        __syncthreads();
    }

    // epilogue
#pragma unroll
    for (int i = 0; i < 4; i++) {
        int r = m0 + wm + i * 16 + lg;
#pragma unroll
        for (int j = 0; j < 4; j++) {
            int c = n0 + wn + j * 8 + lq * 2;
            float v0 = acc[i][j][0] * scale;
            float v1 = acc[i][j][1] * scale;
            float v2 = acc[i][j][2] * scale;
            float v3 = acc[i][j][3] * scale;
            if (HAS_BIAS) {
                float b0 = bias[c], b1 = bias[c + 1];
                v0 += b0; v1 += b1; v2 += b0; v3 += b1;
            }
            if (HAS_RESID) {
                v0 += resid[(long)r * ldc + c];
                v1 += resid[(long)r * ldc + c + 1];
                v2 += resid[(long)(r + 8) * ldc + c];
                v3 += resid[(long)(r + 8) * ldc + c + 1];
            }
            if constexpr (sizeof(OutT) == 2) {
                *reinterpret_cast<__nv_bfloat162*>(&C[(long)r * ldc + c]) =
                    __floats2bfloat162_rn(v0, v1);
                *reinterpret_cast<__nv_bfloat162*>(&C[(long)(r + 8) * ldc + c]) =
                    __floats2bfloat162_rn(v2, v3);
            } else {
                *reinterpret_cast<float2*>(&C[(long)r * ldc + c])       = make_float2(v0, v1);
                *reinterpret_cast<float2*>(&C[(long)(r + 8) * ldc + c]) = make_float2(v2, v3);
            }
        }
    }
}

// ---- fp32 -> bf16 convert (n multiple of 4) ----
__global__ __launch_bounds__(256) void cvt_k(const float* __restrict__ in,
                                             __nv_bfloat16* __restrict__ out, int n)
{
    int i = (blockIdx.x * 256 + threadIdx.x) * 4;
    if (i < n) {
        float4 v = *reinterpret_cast<const float4*>(in + i);
        *reinterpret_cast<__nv_bfloat162*>(out + i)     = __floats2bfloat162_rn(v.x, v.y);
        *reinterpret_cast<__nv_bfloat162*>(out + i + 2) = __floats2bfloat162_rn(v.z, v.w);
    }
}

// ---- bf16 transpose per batch: [SEQ,DIM] -> [DIM,SEQ] ----
__global__ __launch_bounds__(256) void transpose_bf(const __nv_bfloat16* __restrict__ in,
                                                    __nv_bfloat16* __restrict__ out)
{
    __shared__ __nv_bfloat16 t[32][33];
    const size_t boff = (size_t)blockIdx.z * SEQ * DIM;
    const int x0 = blockIdx.x * 32;   // dim
    const int y0 = blockIdx.y * 32;   // seq
    const int tx = threadIdx.x;
    const int ty = threadIdx.y;       // 0..7
#pragma unroll
    for (int i = 0; i < 32; i += 8)
        t[ty + i][tx] = in[boff + (size_t)(y0 + ty + i) * DIM + x0 + tx];
    __syncthreads();
#pragma unroll
    for (int i = 0; i < 32; i += 8)
        out[boff + (size_t)(x0 + ty + i) * SEQ + y0 + tx] = t[tx][ty + i];
}

// ---- row softmax (fp32 in, bf16 out), row length 2048 ----
__global__ __launch_bounds__(256) void softmax_k(const float* __restrict__ S,
                                                 __nv_bfloat16* __restrict__ P)
{
    const float* pin = S + (long)blockIdx.x * SEQ;
    __nv_bfloat16* pout = P + (long)blockIdx.x * SEQ;
    const int tid = threadIdx.x;
    float vals[8];
    float mx = -1e30f;
#pragma unroll
    for (int i = 0; i < 8; i++) {
        vals[i] = pin[tid + i * 256];
        mx = fmaxf(mx, vals[i]);
    }
#pragma unroll
    for (int o = 16; o; o >>= 1) mx = fmaxf(mx, __shfl_xor_sync(0xFFFFFFFFu, mx, o));
    __shared__ float redm[8];
    if ((tid & 31) == 0) redm[tid >> 5] = mx;
    __syncthreads();
    mx = redm[0];
#pragma unroll
    for (int i = 1; i < 8; i++) mx = fmaxf(mx, redm[i]);

    float sum = 0.f;
#pragma unroll
    for (int i = 0; i < 8; i++) {
        vals[i] = expf(vals[i] - mx);
        sum += vals[i];
    }
#pragma unroll
    for (int o = 16; o; o >>= 1) sum += __shfl_xor_sync(0xFFFFFFFFu, sum, o);
    __shared__ float reds[8];
    if ((tid & 31) == 0) reds[tid >> 5] = sum;
    __syncthreads();
    sum = 0.f;
#pragma unroll
    for (int i = 0; i < 8; i++) sum += reds[i];
    const float inv = 1.f / sum;
#pragma unroll
    for (int i = 0; i < 8; i++) pout[tid + i * 256] = __float2bfloat16(vals[i] * inv);
}

// ---- in-place LayerNorm over rows of 1024 fp32 ----
__global__ __launch_bounds__(256) void ln_k(float* __restrict__ y,
                                            const float* __restrict__ gamma,
                                            const float* __restrict__ beta)
{
    float* p = y + (long)blockIdx.x * DIM;
    const int tid = threadIdx.x;
    float4 v = reinterpret_cast<float4*>(p)[tid];
    float s  = v.x + v.y + v.z + v.w;
    float sq = v.x * v.x + v.y * v.y + v.z * v.z + v.w * v.w;
#pragma unroll
    for (int o = 16; o; o >>= 1) {
        s  += __shfl_xor_sync(0xFFFFFFFFu, s, o);
        sq += __shfl_xor_sync(0xFFFFFFFFu, sq, o);
    }
    __shared__ float rs_[8], rq_[8];
    if ((tid & 31) == 0) { rs_[tid >> 5] = s; rq_[tid >> 5] = sq; }
    __syncthreads();
    s = 0.f; sq = 0.f;
#pragma unroll
    for (int i = 0; i < 8; i++) { s += rs_[i]; sq += rq_[i]; }
    const float mean = s * (1.f / DIM);
    const float var  = sq * (1.f / DIM) - mean * mean;
    const float inv  = rsqrtf(var + 1e-5f);
    const float4 g = reinterpret_cast<const float4*>(gamma)[tid];
    const float4 b = reinterpret_cast<const float4*>(beta)[tid];
    v.x = (v.x - mean) * inv * g.x + b.x;
    v.y = (v.y - mean) * inv * g.y + b.y;
    v.z = (v.z - mean) * inv * g.z + b.z;
    v.w = (v.w - mean) * inv * g.w + b.w;
    reinterpret_cast<float4*>(p)[tid] = v;
}

extern "C" void kernel_launch(void* const* d_in, const int* in_sizes, int n_in,
                              void* d_out, int out_size)
{
    const float* x     = (const float*)d_in[0];
    const float* Wq    = (const float*)d_in[1];
    const float* bq    = (const float*)d_in[2];
    const float* Wk    = (const float*)d_in[3];
    const float* bk    = (const float*)d_in[4];
    const float* Wv    = (const float*)d_in[5];
    const float* bv    = (const float*)d_in[6];
    const float* Wo    = (const float*)d_in[7];
    const float* bo    = (const float*)d_in[8];
    const float* gamma = (const float*)d_in[9];
    const float* beta  = (const float*)d_in[10];
    float* out = (float*)d_out;

    void *pxb, *pwq, *pwk, *pwv, *pwo, *pQ, *pK, *pV, *pVt, *pS, *pP, *pW;
    cudaGetSymbolAddress(&pxb, g_xb);
    cudaGetSymbolAddress(&pwq, g_Wqb);
    cudaGetSymbolAddress(&pwk, g_Wkb);
    cudaGetSymbolAddress(&pwv, g_Wvb);
    cudaGetSymbolAddress(&pwo, g_Wob);
    cudaGetSymbolAddress(&pQ,  g_Qb);
    cudaGetSymbolAddress(&pK,  g_Kb);
    cudaGetSymbolAddress(&pV,  g_Vb);
    cudaGetSymbolAddress(&pVt, g_Vt);
    cudaGetSymbolAddress(&pS,  g_S);
    cudaGetSymbolAddress(&pP,  g_P);
    cudaGetSymbolAddress(&pW,  g_Wt);
    __nv_bfloat16* xb  = (__nv_bfloat16*)pxb;
    __nv_bfloat16* Wqb = (__nv_bfloat16*)pwq;
    __nv_bfloat16* Wkb = (__nv_bfloat16*)pwk;
    __nv_bfloat16* Wvb = (__nv_bfloat16*)pwv;
    __nv_bfloat16* Wob = (__nv_bfloat16*)pwo;
    __nv_bfloat16* Qb  = (__nv_bfloat16*)pQ;
    __nv_bfloat16* Kb  = (__nv_bfloat16*)pK;
    __nv_bfloat16* Vb  = (__nv_bfloat16*)pV;
    __nv_bfloat16* Vt  = (__nv_bfloat16*)pVt;
    float*         Sc  = (float*)pS;
    __nv_bfloat16* P   = (__nv_bfloat16*)pP;
    __nv_bfloat16* Wt  = (__nv_bfloat16*)pW;

    dim3 blk(256);

    // 0) convert inputs to bf16
    {
        int n = MTOT * DIM;
        cvt_k<<<(n / 4 + 255) / 256, blk>>>(x, xb, n);
        int nw = DIM * DIM;
        int gb = (nw / 4 + 255) / 256;
        cvt_k<<<gb, blk>>>(Wq, Wqb, nw);
        cvt_k<<<gb, blk>>>(Wk, Wkb, nw);
        cvt_k<<<gb, blk>>>(Wv, Wvb, nw);
        cvt_k<<<gb, blk>>>(Wo, Wob, nw);
    }

    // 1) QKV projections (bf16 out)
    dim3 gP_(DIM / BN, MTOT / BM, 1);
    gemm_bf<__nv_bfloat16, true, false><<<gP_, blk>>>(xb, Wqb, bq, nullptr, Qb,
        DIM, DIM, DIM, DIM, 1.f, 0, 0, 0);
    gemm_bf<__nv_bfloat16, true, false><<<gP_, blk>>>(xb, Wkb, bk, nullptr, Kb,
        DIM, DIM, DIM, DIM, 1.f, 0, 0, 0);
    gemm_bf<__nv_bfloat16, true, false><<<gP_, blk>>>(xb, Wvb, bv, nullptr, Vb,
        DIM, DIM, DIM, DIM, 1.f, 0, 0, 0);

    // 2) transpose V -> Vt [B][DIM][SEQ]
    transpose_bf<<<dim3(DIM / 32, SEQ / 32, BATCH), dim3(32, 8)>>>(Vb, Vt);

    // 3) scores = Q K^T / 32 (fp32 out)
    dim3 gS_(SEQ / BN, SEQ / BM, BATCH);
    gemm_bf<float, false, false><<<gS_, blk>>>(Qb, Kb, nullptr, nullptr, Sc,
        DIM, DIM, SEQ, DIM, 0.03125f,
        (long)SEQ * DIM, (long)SEQ * DIM, (long)SEQ * SEQ);

    // 4) softmax (bf16 probs)
    softmax_k<<<BATCH * SEQ, blk>>>(Sc, P);

    // 5) weighted = P Vt^T (bf16 out)
    dim3 gW_(DIM / BN, SEQ / BM, BATCH);
    gemm_bf<__nv_bfloat16, false, false><<<gW_, blk>>>(P, Vt, nullptr, nullptr, Wt,
        SEQ, SEQ, DIM, SEQ, 1.f,
        (long)SEQ * SEQ, (long)SEQ * DIM, (long)SEQ * DIM);

    // 6) out = weighted Wo^T + bo + x (fp32)
    gemm_bf<float, true, true><<<gP_, blk>>>(Wt, Wob, bo, x, out,
        DIM, DIM, DIM, DIM, 1.f, 0, 0, 0);

    // 7) LayerNorm
    ln_k<<<MTOT, blk>>>(out, gamma, beta);
}

// round 4
// speedup vs baseline: 2.1119x; 1.1256x over previous
#include <cuda_runtime.h>
#include <cuda_bf16.h>
#include <cstdint>
#include <cstddef>

#define BATCH 8
#define SEQ   2048
#define DIM   1024
#define MTOT  (BATCH*SEQ)   // 16384

#define BM 128
#define BN 128
#define BK 32
#define KSTRIDE 40                       // halves per smem row (32 data + 8 pad)
#define TILE_HALVES (BM*KSTRIDE)         // 5120 halves = 10240 B per tile
#define STAGE_BYTES (2*TILE_HALVES*2)    // A + B = 20480 B
#define STAGES 4

// ---- scratch (device globals; allocation-free per harness rules) ----
__device__ __nv_bfloat16 g_xb[(size_t)MTOT*DIM];
__device__ __nv_bfloat16 g_Wqb[DIM*DIM], g_Wkb[DIM*DIM], g_Wvb[DIM*DIM], g_Wob[DIM*DIM];
__device__ __nv_bfloat16 g_Qb[(size_t)MTOT*DIM];
__device__ __nv_bfloat16 g_Kb[(size_t)MTOT*DIM];
__device__ __nv_bfloat16 g_Vb[(size_t)MTOT*DIM];
__device__ __nv_bfloat16 g_Vt[(size_t)MTOT*DIM];
__device__ float         g_S [(size_t)BATCH*SEQ*SEQ];
__device__ __nv_bfloat16 g_P [(size_t)BATCH*SEQ*SEQ];
__device__ __nv_bfloat16 g_Wt[(size_t)MTOT*DIM];

// ---- helpers ----
__device__ __forceinline__ void cp16(uint32_t saddr, const void* gmem) {
    asm volatile("cp.async.cg.shared.global [%0], [%1], 16;\n" :: "r"(saddr), "l"(gmem));
}
__device__ __forceinline__ void cp_commit() { asm volatile("cp.async.commit_group;\n"); }
template<int N> __device__ __forceinline__ void cp_wait() {
    asm volatile("cp.async.wait_group %0;\n" :: "n"(N));
}
__device__ __forceinline__ void ldsm_x4(uint32_t& r0, uint32_t& r1, uint32_t& r2, uint32_t& r3,
                                        uint32_t addr) {
    asm volatile("ldmatrix.sync.aligned.m8n8.x4.shared.b16 {%0,%1,%2,%3}, [%4];"
                 : "=r"(r0), "=r"(r1), "=r"(r2), "=r"(r3) : "r"(addr));
}
__device__ __forceinline__ void mma_bf16(float c[4], const uint32_t a[4], const uint32_t b[2]) {
    asm("mma.sync.aligned.m16n8k16.row.col.f32.bf16.bf16.f32 "
        "{%0,%1,%2,%3},{%4,%5,%6,%7},{%8,%9},{%0,%1,%2,%3};"
        : "+f"(c[0]), "+f"(c[1]), "+f"(c[2]), "+f"(c[3])
        : "r"(a[0]), "r"(a[1]), "r"(a[2]), "r"(a[3]), "r"(b[0]), "r"(b[1]));
}

// ---- NT bf16 GEMM: C = A[M,K] * B[N,K]^T * scale (+bias) (+resid) ----
// 4-stage cp.async pipeline, ldmatrix fragment loads. M,N mult of 128, K mult of 32.
template<typename OutT, bool HAS_BIAS, bool HAS_RESID>
__global__ __launch_bounds__(256, 2) void gemm_bf(
    const __nv_bfloat16* __restrict__ A, const __nv_bfloat16* __restrict__ B,
    const float* __restrict__ bias, const float* __restrict__ resid,
    OutT* __restrict__ C,
    int lda, int ldb, int ldc, int K, float scale,
    long sA, long sB, long sC)
{
    extern __shared__ __align__(16) __nv_bfloat16 smem[];  // STAGES*(As+Bs)

    const int bz = blockIdx.z;
    A += (long)bz * sA;
    B += (long)bz * sB;
    C += (long)bz * sC;

    const int m0 = blockIdx.y * BM;
    const int n0 = blockIdx.x * BN;
    const int tid  = threadIdx.x;
    const int wid  = tid >> 5;
    const int lane = tid & 31;
    const int wm = (wid >> 2) * 64;   // 2 warps in m
    const int wn = (wid & 3) * 32;    // 4 warps in n
    const int lg = lane >> 2;
    const int lq = lane & 3;

    // loader mapping: 64 rows/pass, 4x 16B chunks per row
    const int lr = tid >> 2;          // 0..63
    const int lc = (tid & 3) * 8;     // half offset 0,8,16,24

    // ldmatrix lane address components (in halves, relative to tile base)
    const int a_row = wm + (lane & 15);           // + i*16
    const int a_ksel = (lane >> 4) * 8;           // + s*16
    const int b_row = wn + (lane & 7) + ((lane >> 4) & 1) * 8;   // + jp*16
    const int b_ksel = ((lane >> 3) & 1) * 8;

    const uint32_t smem_base = (uint32_t)__cvta_generic_to_shared(smem);

    float acc[4][4][4];
#pragma unroll
    for (int i = 0; i < 4; i++)
#pragma unroll
        for (int j = 0; j < 4; j++)
#pragma unroll
            for (int r = 0; r < 4; r++) acc[i][j][r] = 0.f;

    const int KT = K / BK;

    auto load_stage = [&](int buf, int kt) {
        const int k0 = kt * BK;
        const uint32_t as = smem_base + buf * STAGE_BYTES;
        const uint32_t bs = as + TILE_HALVES * 2;
#pragma unroll
        for (int p = 0; p < 2; p++) {
            int row = lr + p * 64;
            cp16(as + (row * KSTRIDE + lc) * 2, A + (long)(m0 + row) * lda + k0 + lc);
            cp16(bs + (row * KSTRIDE + lc) * 2, B + (long)(n0 + row) * ldb + k0 + lc);
        }
        cp_commit();
    };

    // prologue: fill 3 stages
    load_stage(0, 0);
    if (KT > 1) load_stage(1, 1);
    if (KT > 2) load_stage(2, 2);

    for (int kt = 0; kt < KT; kt++) {
        const int buf = kt & (STAGES - 1);
        if (KT > 2) cp_wait<2>(); else cp_wait<0>();
        __syncthreads();

        // issue next stage's loads before computing (overlap)
        if (kt + 3 < KT) load_stage((kt + 3) & (STAGES - 1), kt + 3);

        const uint32_t as = smem_base + buf * STAGE_BYTES;
        const uint32_t bs = as + TILE_HALVES * 2;

#pragma unroll
        for (int s = 0; s < 2; s++) {
            uint32_t af[4][4];
            uint32_t bfr[4][2];
#pragma unroll
            for (int i = 0; i < 4; i++) {
                uint32_t addr = as + (((a_row + i * 16) * KSTRIDE) + s * 16 + a_ksel) * 2;
                ldsm_x4(af[i][0], af[i][1], af[i][2], af[i][3], addr);
            }
#pragma unroll
            for (int jp = 0; jp < 2; jp++) {
                uint32_t addr = bs + (((b_row + jp * 16) * KSTRIDE) + s * 16 + b_ksel) * 2;
                ldsm_x4(bfr[jp * 2][0], bfr[jp * 2][1], bfr[jp * 2 + 1][0], bfr[jp * 2 + 1][1], addr);
            }
#pragma unroll
            for (int i = 0; i < 4; i++)
#pragma unroll
                for (int j = 0; j < 4; j++)
                    mma_bf16(acc[i][j], af[i], bfr[j]);
        }
        __syncthreads();
    }

    // epilogue
#pragma unroll
    for (int i = 0; i < 4; i++) {
        int r = m0 + wm + i * 16 + lg;
#pragma unroll
        for (int j = 0; j < 4; j++) {
            int c = n0 + wn + j * 8 + lq * 2;
            float v0 = acc[i][j][0] * scale;
            float v1 = acc[i][j][1] * scale;
            float v2 = acc[i][j][2] * scale;
            float v3 = acc[i][j][3] * scale;
            if (HAS_BIAS) {
                float b0 = bias[c], b1 = bias[c + 1];
                v0 += b0; v1 += b1; v2 += b0; v3 += b1;
            }
            if (HAS_RESID) {
                v0 += resid[(long)r * ldc + c];
                v1 += resid[(long)r * ldc + c + 1];
                v2 += resid[(long)(r + 8) * ldc + c];
                v3 += resid[(long)(r + 8) * ldc + c + 1];
            }
            if constexpr (sizeof(OutT) == 2) {
                *reinterpret_cast<__nv_bfloat162*>(&C[(long)r * ldc + c]) =
                    __floats2bfloat162_rn(v0, v1);
                *reinterpret_cast<__nv_bfloat162*>(&C[(long)(r + 8) * ldc + c]) =
                    __floats2bfloat162_rn(v2, v3);
            } else {
                *reinterpret_cast<float2*>(&C[(long)r * ldc + c])       = make_float2(v0, v1);
                *reinterpret_cast<float2*>(&C[(long)(r + 8) * ldc + c]) = make_float2(v2, v3);
            }
        }
    }
}

// ---- fp32 -> bf16 convert ----
__global__ __launch_bounds__(256) void cvt_k(const float* __restrict__ in,
                                             __nv_bfloat16* __restrict__ out, int n)
{
    int i = (blockIdx.x * 256 + threadIdx.x) * 4;
    if (i < n) {
        float4 v = *reinterpret_cast<const float4*>(in + i);
        *reinterpret_cast<__nv_bfloat162*>(out + i)     = __floats2bfloat162_rn(v.x, v.y);
        *reinterpret_cast<__nv_bfloat162*>(out + i + 2) = __floats2bfloat162_rn(v.z, v.w);
    }
}

// ---- bf16 transpose per batch: [SEQ,DIM] -> [DIM,SEQ] ----
__global__ __launch_bounds__(256) void transpose_bf(const __nv_bfloat16* __restrict__ in,
                                                    __nv_bfloat16* __restrict__ out)
{
    __shared__ __nv_bfloat16 t[32][33];
    const size_t boff = (size_t)blockIdx.z * SEQ * DIM;
    const int x0 = blockIdx.x * 32;
    const int y0 = blockIdx.y * 32;
    const int tx = threadIdx.x;
    const int ty = threadIdx.y;
#pragma unroll
    for (int i = 0; i < 32; i += 8)
        t[ty + i][tx] = in[boff + (size_t)(y0 + ty + i) * DIM + x0 + tx];
    __syncthreads();
#pragma unroll
    for (int i = 0; i < 32; i += 8)
        out[boff + (size_t)(x0 + ty + i) * SEQ + y0 + tx] = t[tx][ty + i];
}

// ---- row softmax (fp32 in, bf16 out), row length 2048 ----
__global__ __launch_bounds__(256) void softmax_k(const float* __restrict__ S,
                                                 __nv_bfloat16* __restrict__ P)
{
    const float* pin = S + (long)blockIdx.x * SEQ;
    __nv_bfloat16* pout = P + (long)blockIdx.x * SEQ;
    const int tid = threadIdx.x;
    float vals[8];
    float mx = -1e30f;
#pragma unroll
    for (int i = 0; i < 8; i++) {
        vals[i] = pin[tid + i * 256];
        mx = fmaxf(mx, vals[i]);
    }
#pragma unroll
    for (int o = 16; o; o >>= 1) mx = fmaxf(mx, __shfl_xor_sync(0xFFFFFFFFu, mx, o));
    __shared__ float redm[8];
    if ((tid & 31) == 0) redm[tid >> 5] = mx;
    __syncthreads();
    mx = redm[0];
#pragma unroll
    for (int i = 1; i < 8; i++) mx = fmaxf(mx, redm[i]);

    float sum = 0.f;
#pragma unroll
    for (int i = 0; i < 8; i++) {
        vals[i] = expf(vals[i] - mx);
        sum += vals[i];
    }
#pragma unroll
    for (int o = 16; o; o >>= 1) sum += __shfl_xor_sync(0xFFFFFFFFu, sum, o);
    __shared__ float reds[8];
    if ((tid & 31) == 0) reds[tid >> 5] = sum;
    __syncthreads();
    sum = 0.f;
#pragma unroll
    for (int i = 0; i < 8; i++) sum += reds[i];
    const float inv = 1.f / sum;
#pragma unroll
    for (int i = 0; i < 8; i++) pout[tid + i * 256] = __float2bfloat16(vals[i] * inv);
}

// ---- in-place LayerNorm over rows of 1024 fp32 ----
__global__ __launch_bounds__(256) void ln_k(float* __restrict__ y,
                                            const float* __restrict__ gamma,
                                            const float* __restrict__ beta)
{
    float* p = y + (long)blockIdx.x * DIM;
    const int tid = threadIdx.x;
    float4 v = reinterpret_cast<float4*>(p)[tid];
    float s  = v.x + v.y + v.z + v.w;
    float sq = v.x * v.x + v.y * v.y + v.z * v.z + v.w * v.w;
#pragma unroll
    for (int o = 16; o; o >>= 1) {
        s  += __shfl_xor_sync(0xFFFFFFFFu, s, o);
        sq += __shfl_xor_sync(0xFFFFFFFFu, sq, o);
    }
    __shared__ float rs_[8], rq_[8];
    if ((tid & 31) == 0) { rs_[tid >> 5] = s; rq_[tid >> 5] = sq; }
    __syncthreads();
    s = 0.f; sq = 0.f;
#pragma unroll
    for (int i = 0; i < 8; i++) { s += rs_[i]; sq += rq_[i]; }
    const float mean = s * (1.f / DIM);
    const float var  = sq * (1.f / DIM) - mean * mean;
    const float inv  = rsqrtf(var + 1e-5f);
    const float4 g = reinterpret_cast<const float4*>(gamma)[tid];
    const float4 b = reinterpret_cast<const float4*>(beta)[tid];
    v.x = (v.x - mean) * inv * g.x + b.x;
    v.y = (v.y - mean) * inv * g.y + b.y;
    v.z = (v.z - mean) * inv * g.z + b.z;
    v.w = (v.w - mean) * inv * g.w + b.w;
    reinterpret_cast<float4*>(p)[tid] = v;
}

extern "C" void kernel_launch(void* const* d_in, const int* in_sizes, int n_in,
                              void* d_out, int out_size)
{
    const float* x     = (const float*)d_in[0];
    const float* Wq    = (const float*)d_in[1];
    const float* bq    = (const float*)d_in[2];
    const float* Wk    = (const float*)d_in[3];
    const float* bk    = (const float*)d_in[4];
    const float* Wv    = (const float*)d_in[5];
    const float* bv    = (const float*)d_in[6];
    const float* Wo    = (const float*)d_in[7];
    const float* bo    = (const float*)d_in[8];
    const float* gamma = (const float*)d_in[9];
    const float* beta  = (const float*)d_in[10];
    float* out = (float*)d_out;

    void *pxb, *pwq, *pwk, *pwv, *pwo, *pQ, *pK, *pV, *pVt, *pS, *pP, *pW;
    cudaGetSymbolAddress(&pxb, g_xb);
    cudaGetSymbolAddress(&pwq, g_Wqb);
    cudaGetSymbolAddress(&pwk, g_Wkb);
    cudaGetSymbolAddress(&pwv, g_Wvb);
    cudaGetSymbolAddress(&pwo, g_Wob);
    cudaGetSymbolAddress(&pQ,  g_Qb);
    cudaGetSymbolAddress(&pK,  g_Kb);
    cudaGetSymbolAddress(&pV,  g_Vb);
    cudaGetSymbolAddress(&pVt, g_Vt);
    cudaGetSymbolAddress(&pS,  g_S);
    cudaGetSymbolAddress(&pP,  g_P);
    cudaGetSymbolAddress(&pW,  g_Wt);
    __nv_bfloat16* xb  = (__nv_bfloat16*)pxb;
    __nv_bfloat16* Wqb = (__nv_bfloat16*)pwq;
    __nv_bfloat16* Wkb = (__nv_bfloat16*)pwk;
    __nv_bfloat16* Wvb = (__nv_bfloat16*)pwv;
    __nv_bfloat16* Wob = (__nv_bfloat16*)pwo;
    __nv_bfloat16* Qb  = (__nv_bfloat16*)pQ;
    __nv_bfloat16* Kb  = (__nv_bfloat16*)pK;
    __nv_bfloat16* Vb  = (__nv_bfloat16*)pV;
    __nv_bfloat16* Vt  = (__nv_bfloat16*)pVt;
    float*         Sc  = (float*)pS;
    __nv_bfloat16* P   = (__nv_bfloat16*)pP;
    __nv_bfloat16* Wt  = (__nv_bfloat16*)pW;

    const int SMEM = STAGES * STAGE_BYTES;  // 81920
    cudaFuncSetAttribute(gemm_bf<__nv_bfloat16, true,  false>, cudaFuncAttributeMaxDynamicSharedMemorySize, SMEM);
    cudaFuncSetAttribute(gemm_bf<float,         false, false>, cudaFuncAttributeMaxDynamicSharedMemorySize, SMEM);
    cudaFuncSetAttribute(gemm_bf<__nv_bfloat16, false, false>, cudaFuncAttributeMaxDynamicSharedMemorySize, SMEM);
    cudaFuncSetAttribute(gemm_bf<float,         true,  true >, cudaFuncAttributeMaxDynamicSharedMemorySize, SMEM);

    dim3 blk(256);

    // 0) convert inputs to bf16
    {
        int n = MTOT * DIM;
        cvt_k<<<(n / 4 + 255) / 256, blk>>>(x, xb, n);
        int nw = DIM * DIM;
        int gb = (nw / 4 + 255) / 256;
        cvt_k<<<gb, blk>>>(Wq, Wqb, nw);
        cvt_k<<<gb, blk>>>(Wk, Wkb, nw);
        cvt_k<<<gb, blk>>>(Wv, Wvb, nw);
        cvt_k<<<gb, blk>>>(Wo, Wob, nw);
    }

    // 1) QKV projections (bf16 out)
    dim3 gP_(DIM / BN, MTOT / BM, 1);
    gemm_bf<__nv_bfloat16, true, false><<<gP_, blk, SMEM>>>(xb, Wqb, bq, nullptr, Qb,
        DIM, DIM, DIM, DIM, 1.f, 0, 0, 0);
    gemm_bf<__nv_bfloat16, true, false><<<gP_, blk, SMEM>>>(xb, Wkb, bk, nullptr, Kb,
        DIM, DIM, DIM, DIM, 1.f, 0, 0, 0);
    gemm_bf<__nv_bfloat16, true, false><<<gP_, blk, SMEM>>>(xb, Wvb, bv, nullptr, Vb,
        DIM, DIM, DIM, DIM, 1.f, 0, 0, 0);

    // 2) transpose V -> Vt [B][DIM][SEQ]
    transpose_bf<<<dim3(DIM / 32, SEQ / 32, BATCH), dim3(32, 8)>>>(Vb, Vt);

    // 3) scores = Q K^T / 32 (fp32 out)
    dim3 gS_(SEQ / BN, SEQ / BM, BATCH);
    gemm_bf<float, false, false><<<gS_, blk, SMEM>>>(Qb, Kb, nullptr, nullptr, Sc,
        DIM, DIM, SEQ, DIM, 0.03125f,
        (long)SEQ * DIM, (long)SEQ * DIM, (long)SEQ * SEQ);

    // 4) softmax (bf16 probs)
    softmax_k<<<BATCH * SEQ, blk>>>(Sc, P);

    // 5) weighted = P Vt^T (bf16 out)
    dim3 gW_(DIM / BN, SEQ / BM, BATCH);
    gemm_bf<__nv_bfloat16, false, false><<<gW_, blk, SMEM>>>(P, Vt, nullptr, nullptr, Wt,
        SEQ, SEQ, DIM, SEQ, 1.f,
        (long)SEQ * SEQ, (long)SEQ * DIM, (long)SEQ * DIM);

    // 6) out = weighted Wo^T + bo + x (fp32, residual fused)
    gemm_bf<float, true, true><<<gP_, blk, SMEM>>>(Wt, Wob, bo, x, out,
        DIM, DIM, DIM, DIM, 1.f, 0, 0, 0);

    // 7) LayerNorm
    ln_k<<<MTOT, blk>>>(out, gamma, beta);
}

// round 5
// speedup vs baseline: 2.1984x; 1.0410x over previous
#include <cuda_runtime.h>
#include <cuda_bf16.h>
#include <cstdint>
#include <cstddef>

#define BATCH 8
#define SEQ   2048
#define DIM   1024
#define MTOT  (BATCH*SEQ)   // 16384

#define BM 128
#define BN 128
#define BK 32
#define KSTRIDE 40                       // halves per smem row (32 data + 8 pad)
#define TILE_HALVES (BM*KSTRIDE)         // 5120 halves = 10240 B per tile
#define STAGE_BYTES (2*TILE_HALVES*2)    // A + B = 20480 B
#define STAGES 4

// ---- scratch (device globals; allocation-free per harness rules) ----
__device__ __nv_bfloat16 g_xb[(size_t)MTOT*DIM];
__device__ __nv_bfloat16 g_Wqb[DIM*DIM], g_Wkb[DIM*DIM], g_Wvb[DIM*DIM], g_Wob[DIM*DIM];
__device__ __nv_bfloat16 g_Qb[(size_t)MTOT*DIM];
__device__ __nv_bfloat16 g_Kb[(size_t)MTOT*DIM];
__device__ __nv_bfloat16 g_Vb[(size_t)MTOT*DIM];
__device__ __nv_bfloat16 g_Vt[(size_t)MTOT*DIM];
__device__ float         g_S [(size_t)BATCH*SEQ*SEQ];
__device__ __nv_bfloat16 g_P [(size_t)BATCH*SEQ*SEQ];
__device__ __nv_bfloat16 g_Wt[(size_t)MTOT*DIM];

// ---- helpers ----
__device__ __forceinline__ void cp16(uint32_t saddr, const void* gmem) {
    asm volatile("cp.async.cg.shared.global [%0], [%1], 16;\n" :: "r"(saddr), "l"(gmem));
}
__device__ __forceinline__ void cp_commit() { asm volatile("cp.async.commit_group;\n"); }
template<int N> __device__ __forceinline__ void cp_wait() {
    asm volatile("cp.async.wait_group %0;\n" :: "n"(N));
}
__device__ __forceinline__ void ldsm_x4(uint32_t& r0, uint32_t& r1, uint32_t& r2, uint32_t& r3,
                                        uint32_t addr) {
    asm volatile("ldmatrix.sync.aligned.m8n8.x4.shared.b16 {%0,%1,%2,%3}, [%4];"
                 : "=r"(r0), "=r"(r1), "=r"(r2), "=r"(r3) : "r"(addr));
}
__device__ __forceinline__ void mma_bf16(float c[4], const uint32_t a[4], const uint32_t b[2]) {
    asm("mma.sync.aligned.m16n8k16.row.col.f32.bf16.bf16.f32 "
        "{%0,%1,%2,%3},{%4,%5,%6,%7},{%8,%9},{%0,%1,%2,%3};"
        : "+f"(c[0]), "+f"(c[1]), "+f"(c[2]), "+f"(c[3])
        : "r"(a[0]), "r"(a[1]), "r"(a[2]), "r"(a[3]), "r"(b[0]), "r"(b[1]));
}

// ---- NT bf16 GEMM: C = A[M,K] * B[N,K]^T * scale (+bias) (+resid) ----
// 128 threads / 4 warps, warp tile 64x64. 4-stage cp.async pipeline + ldmatrix.
template<typename OutT, bool HAS_BIAS, bool HAS_RESID>
__global__ __launch_bounds__(128, 2) void gemm_bf(
    const __nv_bfloat16* __restrict__ A, const __nv_bfloat16* __restrict__ B,
    const float* __restrict__ bias, const float* __restrict__ resid,
    OutT* __restrict__ C,
    int lda, int ldb, int ldc, int K, float scale,
    long sA, long sB, long sC)
{
    extern __shared__ __align__(16) __nv_bfloat16 smem[];  // STAGES*(As+Bs)

    const int bz = blockIdx.z;
    A += (long)bz * sA;
    B += (long)bz * sB;
    C += (long)bz * sC;

    const int m0 = blockIdx.y * BM;
    const int n0 = blockIdx.x * BN;
    const int tid  = threadIdx.x;
    const int wid  = tid >> 5;
    const int lane = tid & 31;
    const int wm = (wid >> 1) * 64;   // 2 warps in m
    const int wn = (wid & 1) * 64;    // 2 warps in n
    const int lg = lane >> 2;
    const int lq = lane & 3;

    // loader mapping: 32 rows/pass, 4x 16B chunks per row, 4 passes per tile
    const int lr = tid >> 2;          // 0..31
    const int lc = (tid & 3) * 8;     // half offset 0,8,16,24

    // ldmatrix lane address components (halves, relative to tile base)
    const int a_row = wm + (lane & 15);                           // + i*16
    const int a_ksel = (lane >> 4) * 8;                           // + s*16
    const int b_row = wn + (lane & 7) + ((lane >> 4) & 1) * 8;    // + jp*16
    const int b_ksel = ((lane >> 3) & 1) * 8;

    const uint32_t smem_base = (uint32_t)__cvta_generic_to_shared(smem);

    float acc[4][8][4];
#pragma unroll
    for (int i = 0; i < 4; i++)
#pragma unroll
        for (int j = 0; j < 8; j++)
#pragma unroll
            for (int r = 0; r < 4; r++) acc[i][j][r] = 0.f;

    const int KT = K / BK;

    auto load_stage = [&](int buf, int kt) {
        const int k0 = kt * BK;
        const uint32_t as = smem_base + buf * STAGE_BYTES;
        const uint32_t bs = as + TILE_HALVES * 2;
#pragma unroll
        for (int p = 0; p < 4; p++) {
            int row = lr + p * 32;
            cp16(as + (row * KSTRIDE + lc) * 2, A + (long)(m0 + row) * lda + k0 + lc);
            cp16(bs + (row * KSTRIDE + lc) * 2, B + (long)(n0 + row) * ldb + k0 + lc);
        }
        cp_commit();
    };

    // prologue: fill 3 stages
    load_stage(0, 0);
    if (KT > 1) load_stage(1, 1);
    if (KT > 2) load_stage(2, 2);

    for (int kt = 0; kt < KT; kt++) {
        const int buf = kt & (STAGES - 1);
        if (KT > 2) cp_wait<2>(); else cp_wait<0>();
        __syncthreads();

        // issue next stage's loads before computing (overlap)
        if (kt + 3 < KT) load_stage((kt + 3) & (STAGES - 1), kt + 3);

        const uint32_t as = smem_base + buf * STAGE_BYTES;
        const uint32_t bs = as + TILE_HALVES * 2;

#pragma unroll
        for (int s = 0; s < 2; s++) {
            uint32_t af[4][4];
            uint32_t bfr[8][2];
#pragma unroll
            for (int i = 0; i < 4; i++) {
                uint32_t addr = as + (((a_row + i * 16) * KSTRIDE) + s * 16 + a_ksel) * 2;
                ldsm_x4(af[i][0], af[i][1], af[i][2], af[i][3], addr);
            }
#pragma unroll
            for (int jp = 0; jp < 4; jp++) {
                uint32_t addr = bs + (((b_row + jp * 16) * KSTRIDE) + s * 16 + b_ksel) * 2;
                ldsm_x4(bfr[jp * 2][0], bfr[jp * 2][1], bfr[jp * 2 + 1][0], bfr[jp * 2 + 1][1], addr);
            }
#pragma unroll
            for (int i = 0; i < 4; i++)
#pragma unroll
                for (int j = 0; j < 8; j++)
                    mma_bf16(acc[i][j], af[i], bfr[j]);
        }
        __syncthreads();
    }

    // epilogue
#pragma unroll
    for (int i = 0; i < 4; i++) {
        int r = m0 + wm + i * 16 + lg;
#pragma unroll
        for (int j = 0; j < 8; j++) {
            int c = n0 + wn + j * 8 + lq * 2;
            float v0 = acc[i][j][0] * scale;
            float v1 = acc[i][j][1] * scale;
            float v2 = acc[i][j][2] * scale;
            float v3 = acc[i][j][3] * scale;
            if (HAS_BIAS) {
                float b0 = bias[c], b1 = bias[c + 1];
                v0 += b0; v1 += b1; v2 += b0; v3 += b1;
            }
            if (HAS_RESID) {
                v0 += resid[(long)r * ldc + c];
                v1 += resid[(long)r * ldc + c + 1];
                v2 += resid[(long)(r + 8) * ldc + c];
                v3 += resid[(long)(r + 8) * ldc + c + 1];
            }
            if constexpr (sizeof(OutT) == 2) {
                *reinterpret_cast<__nv_bfloat162*>(&C[(long)r * ldc + c]) =
                    __floats2bfloat162_rn(v0, v1);
                *reinterpret_cast<__nv_bfloat162*>(&C[(long)(r + 8) * ldc + c]) =
                    __floats2bfloat162_rn(v2, v3);
            } else {
                *reinterpret_cast<float2*>(&C[(long)r * ldc + c])       = make_float2(v0, v1);
                *reinterpret_cast<float2*>(&C[(long)(r + 8) * ldc + c]) = make_float2(v2, v3);
            }
        }
    }
}

// ---- fp32 -> bf16 convert ----
__global__ __launch_bounds__(256) void cvt_k(const float* __restrict__ in,
                                             __nv_bfloat16* __restrict__ out, int n)
{
    int i = (blockIdx.x * 256 + threadIdx.x) * 4;
    if (i < n) {
        float4 v = *reinterpret_cast<const float4*>(in + i);
        *reinterpret_cast<__nv_bfloat162*>(out + i)     = __floats2bfloat162_rn(v.x, v.y);
        *reinterpret_cast<__nv_bfloat162*>(out + i + 2) = __floats2bfloat162_rn(v.z, v.w);
    }
}

// ---- bf16 transpose per batch: [SEQ,DIM] -> [DIM,SEQ] ----
__global__ __launch_bounds__(256) void transpose_bf(const __nv_bfloat16* __restrict__ in,
                                                    __nv_bfloat16* __restrict__ out)
{
    __shared__ __nv_bfloat16 t[32][33];
    const size_t boff = (size_t)blockIdx.z * SEQ * DIM;
    const int x0 = blockIdx.x * 32;
    const int y0 = blockIdx.y * 32;
    const int tx = threadIdx.x;
    const int ty = threadIdx.y;
#pragma unroll
    for (int i = 0; i < 32; i += 8)
        t[ty + i][tx] = in[boff + (size_t)(y0 + ty + i) * DIM + x0 + tx];
    __syncthreads();
#pragma unroll
    for (int i = 0; i < 32; i += 8)
        out[boff + (size_t)(x0 + ty + i) * SEQ + y0 + tx] = t[tx][ty + i];
}

// ---- row softmax (fp32 in, bf16 out), row length 2048 ----
__global__ __launch_bounds__(256) void softmax_k(const float* __restrict__ S,
                                                 __nv_bfloat16* __restrict__ P)
{
    const float* pin = S + (long)blockIdx.x * SEQ;
    __nv_bfloat16* pout = P + (long)blockIdx.x * SEQ;
    const int tid = threadIdx.x;
    float vals[8];
    float mx = -1e30f;
#pragma unroll
    for (int i = 0; i < 8; i++) {
        vals[i] = pin[tid + i * 256];
        mx = fmaxf(mx, vals[i]);
    }
#pragma unroll
    for (int o = 16; o; o >>= 1) mx = fmaxf(mx, __shfl_xor_sync(0xFFFFFFFFu, mx, o));
    __shared__ float redm[8];
    if ((tid & 31) == 0) redm[tid >> 5] = mx;
    __syncthreads();
    mx = redm[0];
#pragma unroll
    for (int i = 1; i < 8; i++) mx = fmaxf(mx, redm[i]);

    float sum = 0.f;
#pragma unroll
    for (int i = 0; i < 8; i++) {
        vals[i] = expf(vals[i] - mx);
        sum += vals[i];
    }
#pragma unroll
    for (int o = 16; o; o >>= 1) sum += __shfl_xor_sync(0xFFFFFFFFu, sum, o);
    __shared__ float reds[8];
    if ((tid & 31) == 0) reds[tid >> 5] = sum;
    __syncthreads();
    sum = 0.f;
#pragma unroll
    for (int i = 0; i < 8; i++) sum += reds[i];
    const float inv = 1.f / sum;
#pragma unroll
    for (int i = 0; i < 8; i++) pout[tid + i * 256] = __float2bfloat16(vals[i] * inv);
}

// ---- in-place LayerNorm over rows of 1024 fp32 ----
__global__ __launch_bounds__(256) void ln_k(float* __restrict__ y,
                                            const float* __restrict__ gamma,
                                            const float* __restrict__ beta)
{
    float* p = y + (long)blockIdx.x * DIM;
    const int tid = threadIdx.x;
    float4 v = reinterpret_cast<float4*>(p)[tid];
    float s  = v.x + v.y + v.z + v.w;
    float sq = v.x * v.x + v.y * v.y + v.z * v.z + v.w * v.w;
#pragma unroll
    for (int o = 16; o; o >>= 1) {
        s  += __shfl_xor_sync(0xFFFFFFFFu, s, o);
        sq += __shfl_xor_sync(0xFFFFFFFFu, sq, o);
    }
    __shared__ float rs_[8], rq_[8];
    if ((tid & 31) == 0) { rs_[tid >> 5] = s; rq_[tid >> 5] = sq; }
    __syncthreads();
    s = 0.f; sq = 0.f;
#pragma unroll
    for (int i = 0; i < 8; i++) { s += rs_[i]; sq += rq_[i]; }
    const float mean = s * (1.f / DIM);
    const float var  = sq * (1.f / DIM) - mean * mean;
    const float inv  = rsqrtf(var + 1e-5f);
    const float4 g = reinterpret_cast<const float4*>(gamma)[tid];
    const float4 b = reinterpret_cast<const float4*>(beta)[tid];
    v.x = (v.x - mean) * inv * g.x + b.x;
    v.y = (v.y - mean) * inv * g.y + b.y;
    v.z = (v.z - mean) * inv * g.z + b.z;
    v.w = (v.w - mean) * inv * g.w + b.w;
    reinterpret_cast<float4*>(p)[tid] = v;
}

extern "C" void kernel_launch(void* const* d_in, const int* in_sizes, int n_in,
                              void* d_out, int out_size)
{
    const float* x     = (const float*)d_in[0];
    const float* Wq    = (const float*)d_in[1];
    const float* bq    = (const float*)d_in[2];
    const float* Wk    = (const float*)d_in[3];
    const float* bk    = (const float*)d_in[4];
    const float* Wv    = (const float*)d_in[5];
    const float* bv    = (const float*)d_in[6];
    const float* Wo    = (const float*)d_in[7];
    const float* bo    = (const float*)d_in[8];
    const float* gamma = (const float*)d_in[9];
    const float* beta  = (const float*)d_in[10];
    float* out = (float*)d_out;

    void *pxb, *pwq, *pwk, *pwv, *pwo, *pQ, *pK, *pV, *pVt, *pS, *pP, *pW;
    cudaGetSymbolAddress(&pxb, g_xb);
    cudaGetSymbolAddress(&pwq, g_Wqb);
    cudaGetSymbolAddress(&pwk, g_Wkb);
    cudaGetSymbolAddress(&pwv, g_Wvb);
    cudaGetSymbolAddress(&pwo, g_Wob);
    cudaGetSymbolAddress(&pQ,  g_Qb);
    cudaGetSymbolAddress(&pK,  g_Kb);
    cudaGetSymbolAddress(&pV,  g_Vb);
    cudaGetSymbolAddress(&pVt, g_Vt);
    cudaGetSymbolAddress(&pS,  g_S);
    cudaGetSymbolAddress(&pP,  g_P);
    cudaGetSymbolAddress(&pW,  g_Wt);
    __nv_bfloat16* xb  = (__nv_bfloat16*)pxb;
    __nv_bfloat16* Wqb = (__nv_bfloat16*)pwq;
    __nv_bfloat16* Wkb = (__nv_bfloat16*)pwk;
    __nv_bfloat16* Wvb = (__nv_bfloat16*)pwv;
    __nv_bfloat16* Wob = (__nv_bfloat16*)pwo;
    __nv_bfloat16* Qb  = (__nv_bfloat16*)pQ;
    __nv_bfloat16* Kb  = (__nv_bfloat16*)pK;
    __nv_bfloat16* Vb  = (__nv_bfloat16*)pV;
    __nv_bfloat16* Vt  = (__nv_bfloat16*)pVt;
    float*         Sc  = (float*)pS;
    __nv_bfloat16* P   = (__nv_bfloat16*)pP;
    __nv_bfloat16* Wt  = (__nv_bfloat16*)pW;

    const int SMEM = STAGES * STAGE_BYTES;  // 81920
    cudaFuncSetAttribute(gemm_bf<__nv_bfloat16, true,  false>, cudaFuncAttributeMaxDynamicSharedMemorySize, SMEM);
    cudaFuncSetAttribute(gemm_bf<float,         false, false>, cudaFuncAttributeMaxDynamicSharedMemorySize, SMEM);
    cudaFuncSetAttribute(gemm_bf<__nv_bfloat16, false, false>, cudaFuncAttributeMaxDynamicSharedMemorySize, SMEM);
    cudaFuncSetAttribute(gemm_bf<float,         true,  true >, cudaFuncAttributeMaxDynamicSharedMemorySize, SMEM);

    dim3 blk(128);
    dim3 blk256(256);

    // 0) convert inputs to bf16
    {
        int n = MTOT * DIM;
        cvt_k<<<(n / 4 + 255) / 256, blk256>>>(x, xb, n);
        int nw = DIM * DIM;
        int gb = (nw / 4 + 255) / 256;
        cvt_k<<<gb, blk256>>>(Wq, Wqb, nw);
        cvt_k<<<gb, blk256>>>(Wk, Wkb, nw);
        cvt_k<<<gb, blk256>>>(Wv, Wvb, nw);
        cvt_k<<<gb, blk256>>>(Wo, Wob, nw);
    }

    // 1) QKV projections (bf16 out)
    dim3 gP_(DIM / BN, MTOT / BM, 1);
    gemm_bf<__nv_bfloat16, true, false><<<gP_, blk, SMEM>>>(xb, Wqb, bq, nullptr, Qb,
        DIM, DIM, DIM, DIM, 1.f, 0, 0, 0);
    gemm_bf<__nv_bfloat16, true, false><<<gP_, blk, SMEM>>>(xb, Wkb, bk, nullptr, Kb,
        DIM, DIM, DIM, DIM, 1.f, 0, 0, 0);
    gemm_bf<__nv_bfloat16, true, false><<<gP_, blk, SMEM>>>(xb, Wvb, bv, nullptr, Vb,
        DIM, DIM, DIM, DIM, 1.f, 0, 0, 0);

    // 2) transpose V -> Vt [B][DIM][SEQ]
    transpose_bf<<<dim3(DIM / 32, SEQ / 32, BATCH), dim3(32, 8)>>>(Vb, Vt);

    // 3) scores = Q K^T / 32 (fp32 out)
    dim3 gS_(SEQ / BN, SEQ / BM, BATCH);
    gemm_bf<float, false, false><<<gS_, blk, SMEM>>>(Qb, Kb, nullptr, nullptr, Sc,
        DIM, DIM, SEQ, DIM, 0.03125f,
        (long)SEQ * DIM, (long)SEQ * DIM, (long)SEQ * SEQ);

    // 4) softmax (bf16 probs)
    softmax_k<<<BATCH * SEQ, blk256>>>(Sc, P);

    // 5) weighted = P Vt^T (bf16 out)
    dim3 gW_(DIM / BN, SEQ / BM, BATCH);
    gemm_bf<__nv_bfloat16, false, false><<<gW_, blk, SMEM>>>(P, Vt, nullptr, nullptr, Wt,
        SEQ, SEQ, DIM, SEQ, 1.f,
        (long)SEQ * SEQ, (long)SEQ * DIM, (long)SEQ * DIM);

    // 6) out = weighted Wo^T + bo + x (fp32, residual fused)
    gemm_bf<float, true, true><<<gP_, blk, SMEM>>>(Wt, Wob, bo, x, out,
        DIM, DIM, DIM, DIM, 1.f, 0, 0, 0);

    // 7) LayerNorm
    ln_k<<<MTOT, blk256>>>(out, gamma, beta);
}